// round 12
// baseline (speedup 1.0000x reference)
#include <cuda_runtime.h>
#include <cstdint>

// Correlation cost volume via banded tf32 mma.sync, software-pipelined over
// (h, k-chunk) with cp.async double-buffered raw staging + per-step
// convert-once pass into fragment-friendly tf32 smem layouts; 3 blocks/SM.
// out[b,d,h,w] = mean_c( x[b,c,h,w] * y[b,c,h,w-d] ), 0 where w<d (exact via
// zero-padded halo; cp.async zfill).
// Per (b,h,wtile=128): A[i,k]=x[k,w0+i] (128x32), B[s,k]=y[k,w0-48+s] (176x32),
// P = A.B^T banded; warp m computes rows [16m,16m+16) x cols [16m,16m+64).
// K streamed in 4 chunks of 8 channels; accumulators persist across chunks.
// d = 48-(s-i); epilogue stages to St[48-d][i] so per-d gather is a contig row.
//
// R12: B stored permuted Bp[k][s&7][s>>3] so a thread's 8 n-tile B words are
// contiguous -> 4x LDS.64 replaces 16x (LDS.32+cvt) per k-row. tf32 convert
// happens ONCE per word in the convert pass (A in place, B permuted), removing
// all redundant cvts from the MMA loop. MMA k-order unchanged -> identical
// numerics to R8/R11 (rel_err 2.9367e-4).

#define BDIM 8
#define CDIM 32
#define HDIM 256
#define WDIM 512
#define MAXD 48

#define MT   128
#define NT   176
#define NTHR 256
#define HC   8                    // h rows per block
#define KC   8                    // channels per pipeline chunk
#define NCH  (CDIM / KC)          // 4 chunks per h-row
#define NSTEPS (HC * NCH)         // 32

#define AP  136                   // A pitch (words): banks 8k + i, distinct
#define BP  184                   // raw B pitch (words)
#define BPP 216                   // Bp per-k pitch (words)
#define BRS 26                    // Bp r-stride (words)
#define SP  136                   // stage pitch (words)

#define ARAW_W (KC * AP)          // 1088
#define BRAW_W (KC * BP)          // 1472
#define RAW_W  (ARAW_W + BRAW_W)  // 2560 words per buffer
#define AP_OFF (2 * RAW_W)        // 5120: Ap (converted A, single)
#define BP_OFF (AP_OFF + ARAW_W)  // 6208: Bp (converted+permuted B, single)
#define ST_OFF (BP_OFF + KC * BPP)          // 7936
#define ST_WORDS ((MAXD + 1) * SP)          // 6664
#define SMEM_BYTES ((ST_OFF + ST_WORDS) * 4)  // 58400 B -> 3 blocks/SM

#define A_CHUNKS (KC * (MT / 4))  // 256 16B chunks per step
#define B_CHUNKS (KC * (NT / 4))  // 352
#define A_TASKS  (ARAW_W / 4)     // 272 float4 convert tasks (A)
#define B_TASKS  (KC * (BP / 4))  // 368 float4 convert tasks (B, 2/46 dead)

__device__ __forceinline__ uint32_t f2tf32(float v) {
    uint32_t r;
    asm("cvt.rna.tf32.f32 %0, %1;" : "=r"(r) : "f"(v));
    return r;
}
__device__ __forceinline__ uint32_t smem_u32(const void* p) {
    uint32_t a;
    asm("{ .reg .u64 t; cvta.to.shared.u64 t, %1; cvt.u32.u64 %0, t; }" : "=r"(a) : "l"(p));
    return a;
}
__device__ __forceinline__ void cp16(uint32_t dst, const void* src, int src_sz) {
    asm volatile("cp.async.cg.shared.global [%0], [%1], 16, %2;"
                 :: "r"(dst), "l"(src), "r"(src_sz) : "memory");
}
__device__ __forceinline__ void mma_tf32(float* c, const uint32_t* a,
                                         uint32_t b0, uint32_t b1) {
    asm volatile(
        "mma.sync.aligned.m16n8k8.row.col.f32.tf32.tf32.f32 "
        "{%0,%1,%2,%3}, {%4,%5,%6,%7}, {%8,%9}, {%0,%1,%2,%3};"
        : "+f"(c[0]), "+f"(c[1]), "+f"(c[2]), "+f"(c[3])
        : "r"(a[0]), "r"(a[1]), "r"(a[2]), "r"(a[3]), "r"(b0), "r"(b1));
}

__global__ __launch_bounds__(NTHR, 3)
void corr_mma(const float* __restrict__ x, const float* __restrict__ y,
              float* __restrict__ out) {
    extern __shared__ float smem[];
    const uint32_t sb = smem_u32(smem);

    const int tid  = threadIdx.x;
    const int warp = tid >> 5, lane = tid & 31;
    const int w0    = blockIdx.x * MT;
    const int hbase = blockIdx.y * HC;
    const int b     = blockIdx.z;

    const size_t plane = (size_t)HDIM * WDIM;
    const float* xb = x + (size_t)b * CDIM * plane;
    const float* yb = y + (size_t)b * CDIM * plane;

    // ---- cp.async staging of one 8-channel K-chunk of raw (A,B) for step s ----
    auto issue_stage = [&](int s) {
        const int hh = s >> 2, kc = s & 3, pb = s & 1;
        const float* xr = xb + (size_t)(hbase + hh) * WDIM + (size_t)(kc * KC) * plane;
        const float* yr = yb + (size_t)(hbase + hh) * WDIM + (size_t)(kc * KC) * plane;
        const uint32_t abase = sb + (pb * RAW_W) * 4;
        const uint32_t bbase = abase + ARAW_W * 4;
        #pragma unroll 3
        for (int i = tid; i < A_CHUNKS + B_CHUNKS; i += NTHR) {
            if (i < A_CHUNKS) {
                const int k = i >> 5, v = (i & 31) << 2;
                cp16(abase + (k * AP + v) * 4, xr + k * plane + w0 + v, 16);
            } else {
                const int j = i - A_CHUNKS;
                const int k = j / (NT / 4), v = (j % (NT / 4)) << 2;
                const int gw = w0 - MAXD + v;
                cp16(bbase + (k * BP + v) * 4,
                     yr + k * plane + (gw >= 0 ? gw : 0), gw >= 0 ? 16 : 0);
            }
        }
    };

    issue_stage(0);
    asm volatile("cp.async.commit_group;" ::: "memory");

    const int i0 = 16 * warp;
    const int r  = lane >> 2;     // 0..7
    const int cq = lane & 3;      // 0..3
    uint32_t* Ap = reinterpret_cast<uint32_t*>(smem + AP_OFF);   // [KC][AP] tf32
    uint32_t* Bp = reinterpret_cast<uint32_t*>(smem + BP_OFF);   // permuted tf32
    float*    St = smem + ST_OFF;

    float acc[8][4];

    for (int step = 0; step < NSTEPS; step++) {
        const int kc = step & 3;
        const int p  = step & 1;

        // depth-2: issue next copy first so it hides behind this whole step.
        if (step + 1 < NSTEPS) {
            issue_stage(step + 1);
            asm volatile("cp.async.commit_group;" ::: "memory");
            asm volatile("cp.async.wait_group 1;" ::: "memory");
        } else {
            asm volatile("cp.async.wait_group 0;" ::: "memory");
        }
        __syncthreads();   // raw(p) visible; Ap/Bp free (prev MMA passed a barrier)

        // ---- convert pass: raw fp32 -> tf32, once per word ----
        {
            const float* rawA = smem + p * RAW_W;
            const float* rawB = rawA + ARAW_W;
            #pragma unroll 3
            for (int i = tid; i < A_TASKS + B_TASKS; i += NTHR) {
                if (i < A_TASKS) {
                    // A: in-place layout copy [k][i], contiguous STS.128
                    const int k = i / (AP / 4), v4 = (i % (AP / 4)) * 4;
                    if (v4 < MT) {
                        float4 t = *reinterpret_cast<const float4*>(&rawA[k * AP + v4]);
                        uint4 u;
                        u.x = f2tf32(t.x); u.y = f2tf32(t.y);
                        u.z = f2tf32(t.z); u.w = f2tf32(t.w);
                        *reinterpret_cast<uint4*>(&Ap[k * AP + v4]) = u;
                    }
                } else {
                    const int j = i - A_TASKS;
                    const int k = j / (BP / 4), s4 = (j % (BP / 4)) * 4;
                    if (s4 < NT) {
                        float4 t = *reinterpret_cast<const float4*>(&rawB[k * BP + s4]);
                        uint32_t u0 = f2tf32(t.x), u1 = f2tf32(t.y);
                        uint32_t u2 = f2tf32(t.z), u3 = f2tf32(t.w);
                        // Bp[k][(s&7)*BRS + (s>>3)]
                        uint32_t* bk = &Bp[k * BPP];
                        bk[((s4 + 0) & 7) * BRS + ((s4 + 0) >> 3)] = u0;
                        bk[((s4 + 1) & 7) * BRS + ((s4 + 1) >> 3)] = u1;
                        bk[((s4 + 2) & 7) * BRS + ((s4 + 2) >> 3)] = u2;
                        bk[((s4 + 3) & 7) * BRS + ((s4 + 3) >> 3)] = u3;
                    }
                }
            }
        }
        __syncthreads();   // Ap/Bp visible; also: all raw(p) readers done before
                           // the refill of raw(p) issued at step+2's top

        if (kc == 0) {
            #pragma unroll
            for (int t = 0; t < 8; t++)
                #pragma unroll
                for (int q = 0; q < 4; q++) acc[t][q] = 0.f;
        }

        // ---- banded MMA on this 8-channel chunk (1 k-step of 8) ----
        uint32_t a[4];
        a[0] = Ap[cq       * AP + i0 + r];
        a[1] = Ap[cq       * AP + i0 + r + 8];
        a[2] = Ap[(cq + 4) * AP + i0 + r];
        a[3] = Ap[(cq + 4) * AP + i0 + r + 8];

        // B: Bp[k][r*BRS + 2*warp + t], t=0..7 contiguous -> LDS.64 pairs
        const uint32_t* blo = &Bp[cq       * BPP + r * BRS + 2 * warp];
        const uint32_t* bhi = &Bp[(cq + 4) * BPP + r * BRS + 2 * warp];
        #pragma unroll
        for (int tp = 0; tp < 4; tp++) {
            uint2 lo = *reinterpret_cast<const uint2*>(blo + 2 * tp);
            uint2 hi = *reinterpret_cast<const uint2*>(bhi + 2 * tp);
            mma_tf32(acc[2 * tp],     a, lo.x, hi.x);
            mma_tf32(acc[2 * tp + 1], a, lo.y, hi.y);
        }

        if (kc == 3) {
            // ---- scatter into shift-normalized stage St[u = 48-d][i] ----
            #pragma unroll
            for (int t = 0; t < 8; t++) {
                #pragma unroll
                for (int q = 0; q < 4; q++) {
                    const int re = r + (q >= 2 ? 8 : 0);
                    const int sl = 8 * t + 2 * cq + (q & 1);
                    const int u  = sl - re;
                    if (u >= 1 && u <= MAXD)
                        St[u * SP + i0 + re] = acc[t][q];
                }
            }
            __syncthreads();

            // ---- gather row u = 48-d (contiguous) + coalesced STG.128 ----
            const int h = hbase + (step >> 2);
            const float scale = 1.0f / (float)CDIM;
            const int iq = 4 * lane;
            #pragma unroll
            for (int k = 0; k < 6; k++) {
                const int d = warp + 8 * k;
                float4 v = *reinterpret_cast<const float4*>(&St[(MAXD - d) * SP + iq]);
                v.x *= scale; v.y *= scale; v.z *= scale; v.w *= scale;
                *reinterpret_cast<float4*>(
                    out + (((size_t)b * MAXD + d) * HDIM + h) * WDIM + w0 + iq) = v;
            }
            // St WAR vs next scatter: 4 steps away, many barriers between.
        }
    }
}

extern "C" void kernel_launch(void* const* d_in, const int* in_sizes, int n_in,
                              void* d_out, int out_size) {
    const float* x = (const float*)d_in[0];
    const float* y = (const float*)d_in[1];
    float* out = (float*)d_out;

    cudaFuncSetAttribute(corr_mma,
                         cudaFuncAttributeMaxDynamicSharedMemorySize, SMEM_BYTES);

    dim3 grid(WDIM / MT, HDIM / HC, BDIM);   // (4, 32, 8) = 1024 blocks
    corr_mma<<<grid, NTHR, SMEM_BYTES>>>(x, y, out);
}

// round 13
// speedup vs baseline: 1.4233x; 1.4233x over previous
#include <cuda_runtime.h>
#include <cstdint>

// Correlation cost volume via banded tf32 mma.sync, software-pipelined over
// (h, k-chunk) with a 4-deep circular cp.async buffer ring; 3 blocks/SM.
// out[b,d,h,w] = mean_c( x[b,c,h,w] * y[b,c,h,w-d] ), 0 where w<d (exact via
// zero-padded halo; cp.async zfill). tf32(.rna) folded into fragment loads.
// Per (b,h,wtile=128): A[i,k]=x[k,w0+i] (128x32), B[s,k]=y[k,w0-48+s] (176x32),
// P = A.B^T banded; warp m computes rows [16m,16m+16) x cols [16m,16m+64).
// K streamed in 4 chunks of 8 channels; accumulators persist across chunks.
// d = 48-(s-i); epilogue stages to St[48-d][i] so per-d gather is a contig row.
//
// R13 vs R11: pipeline depth 2 -> 4 (KC 16 -> 8, 4 buffers, copies issued 3
// steps ahead) so each cp.async group has ~3 steps of compute to complete;
// wait_group at the top should be a no-op. Inner loop and numerics identical
// to R11 (rel_err 2.9367e-4). Same smem footprint (67.6 KB).

#define BDIM 8
#define CDIM 32
#define HDIM 256
#define WDIM 512
#define MAXD 48

#define MT   128
#define NT   176
#define NTHR 256
#define HC   8                    // h rows per block
#define KC   8                    // channels per pipeline chunk
#define NCH  (CDIM / KC)          // 4 chunks per h-row
#define NSTEPS (HC * NCH)         // 32
#define NBUF 4

#define AP 136                    // A pitch (words), frag loads conflict-free
#define BP 184                    // B pitch (words), frag loads conflict-free
#define SP 136                    // stage pitch (words)
#define A_WORDS (KC * AP)         // 1088
#define B_WORDS (KC * BP)         // 1472
#define BUF_WORDS (A_WORDS + B_WORDS)       // 2560 (10 KB)
#define ST_OFF  (NBUF * BUF_WORDS)          // 10240
#define ST_WORDS ((MAXD + 1) * SP)          // 6664
#define SMEM_BYTES ((ST_OFF + ST_WORDS) * 4)  // 67616 B -> 3 blocks/SM

#define A_CHUNKS (KC * (MT / 4))  // 256 16B chunks per step
#define B_CHUNKS (KC * (NT / 4))  // 352

__device__ __forceinline__ uint32_t f2tf32(float v) {
    uint32_t r;
    asm("cvt.rna.tf32.f32 %0, %1;" : "=r"(r) : "f"(v));
    return r;
}
__device__ __forceinline__ uint32_t smem_u32(const void* p) {
    uint32_t a;
    asm("{ .reg .u64 t; cvta.to.shared.u64 t, %1; cvt.u32.u64 %0, t; }" : "=r"(a) : "l"(p));
    return a;
}
__device__ __forceinline__ void cp16(uint32_t dst, const void* src, int src_sz) {
    asm volatile("cp.async.cg.shared.global [%0], [%1], 16, %2;"
                 :: "r"(dst), "l"(src), "r"(src_sz) : "memory");
}
__device__ __forceinline__ void mma_tf32(float* c, const uint32_t* a,
                                         uint32_t b0, uint32_t b1) {
    asm volatile(
        "mma.sync.aligned.m16n8k8.row.col.f32.tf32.tf32.f32 "
        "{%0,%1,%2,%3}, {%4,%5,%6,%7}, {%8,%9}, {%0,%1,%2,%3};"
        : "+f"(c[0]), "+f"(c[1]), "+f"(c[2]), "+f"(c[3])
        : "r"(a[0]), "r"(a[1]), "r"(a[2]), "r"(a[3]), "r"(b0), "r"(b1));
}

__global__ __launch_bounds__(NTHR, 3)
void corr_mma(const float* __restrict__ x, const float* __restrict__ y,
              float* __restrict__ out) {
    extern __shared__ float smem[];
    const uint32_t sb = smem_u32(smem);

    const int tid  = threadIdx.x;
    const int warp = tid >> 5, lane = tid & 31;
    const int w0    = blockIdx.x * MT;
    const int hbase = blockIdx.y * HC;
    const int b     = blockIdx.z;

    const size_t plane = (size_t)HDIM * WDIM;
    const float* xb = x + (size_t)b * CDIM * plane;
    const float* yb = y + (size_t)b * CDIM * plane;

    // ---- cp.async staging of one 8-channel K-chunk of (A,B) for step s ----
    auto issue_stage = [&](int s) {
        const int hh = s >> 2, kc = s & 3, pb = s & (NBUF - 1);
        const float* xr = xb + (size_t)(hbase + hh) * WDIM + (size_t)(kc * KC) * plane;
        const float* yr = yb + (size_t)(hbase + hh) * WDIM + (size_t)(kc * KC) * plane;
        const uint32_t abase = sb + (pb * BUF_WORDS) * 4;
        const uint32_t bbase = abase + A_WORDS * 4;
        #pragma unroll 3
        for (int i = tid; i < A_CHUNKS + B_CHUNKS; i += NTHR) {
            if (i < A_CHUNKS) {
                const int k = i >> 5, v = (i & 31) << 2;
                cp16(abase + (k * AP + v) * 4, xr + k * plane + w0 + v, 16);
            } else {
                const int j = i - A_CHUNKS;
                const int k = j / (NT / 4), v = (j % (NT / 4)) << 2;
                const int gw = w0 - MAXD + v;
                cp16(bbase + (k * BP + v) * 4,
                     yr + k * plane + (gw >= 0 ? gw : 0), gw >= 0 ? 16 : 0);
            }
        }
    };

    // prologue: fill the ring 3 deep
    issue_stage(0);
    asm volatile("cp.async.commit_group;" ::: "memory");
    issue_stage(1);
    asm volatile("cp.async.commit_group;" ::: "memory");
    issue_stage(2);
    asm volatile("cp.async.commit_group;" ::: "memory");

    const int i0 = 16 * warp;
    const int r  = lane >> 2;     // 0..7
    const int cq = lane & 3;      // 0..3
    float* St = smem + ST_OFF;

    float acc[8][4];

    for (int step = 0; step < NSTEPS; step++) {
        const int kc = step & 3;
        const int p  = step & (NBUF - 1);

        // issue copy 3 steps ahead (its buffer's readers, step-1, are behind
        // the end-of-step barrier every step executes), then wait for THIS
        // step's group: with g groups younger in flight, wait_group g.
        if (step + 3 < NSTEPS) {
            issue_stage(step + 3);
            asm volatile("cp.async.commit_group;" ::: "memory");
            asm volatile("cp.async.wait_group 3;" ::: "memory");
        } else if (step + 3 == NSTEPS) {
            asm volatile("cp.async.wait_group 2;" ::: "memory");
        } else if (step + 2 == NSTEPS) {
            asm volatile("cp.async.wait_group 1;" ::: "memory");
        } else {
            asm volatile("cp.async.wait_group 0;" ::: "memory");
        }
        __syncthreads();   // buffer p's data visible to all threads

        if (kc == 0) {
            #pragma unroll
            for (int t = 0; t < 8; t++)
                #pragma unroll
                for (int q = 0; q < 4; q++) acc[t][q] = 0.f;
        }

        // ---- banded MMA on chunk p (8 channels = 1 k-step of 8) ----
        const float* As = smem + p * BUF_WORDS;   // [KC][AP] fp32
        const float* Bs = As + A_WORDS;           // [KC][BP] fp32

        uint32_t a[4];
        a[0] = f2tf32(As[cq       * AP + i0 + r]);
        a[1] = f2tf32(As[cq       * AP + i0 + r + 8]);
        a[2] = f2tf32(As[(cq + 4) * AP + i0 + r]);
        a[3] = f2tf32(As[(cq + 4) * AP + i0 + r + 8]);
        #pragma unroll
        for (int t = 0; t < 8; t++) {
            const int s0 = i0 + 8 * t;
            uint32_t b0 = f2tf32(Bs[cq       * BP + s0 + r]);
            uint32_t b1 = f2tf32(Bs[(cq + 4) * BP + s0 + r]);
            mma_tf32(acc[t], a, b0, b1);
        }

        if (kc != 3) {
            __syncthreads();   // end-of-step barrier: orders this step's MMA
                               // reads before the refill of this buffer
                               // (issued at step+1's top targets p+3 != p;
                               // p is re-targeted at step+4, many barriers away)
        } else {
            // ---- scatter into shift-normalized stage St[u = 48-d][i] ----
            #pragma unroll
            for (int t = 0; t < 8; t++) {
                #pragma unroll
                for (int q = 0; q < 4; q++) {
                    const int re = r + (q >= 2 ? 8 : 0);
                    const int sl = 8 * t + 2 * cq + (q & 1);
                    const int u  = sl - re;
                    if (u >= 1 && u <= MAXD)
                        St[u * SP + i0 + re] = acc[t][q];
                }
            }
            __syncthreads();   // doubles as end-of-step barrier

            // ---- gather row u = 48-d (contiguous) + coalesced STG.128 ----
            const int h = hbase + (step >> 2);
            const float scale = 1.0f / (float)CDIM;
            const int iq = 4 * lane;
            #pragma unroll
            for (int k = 0; k < 6; k++) {
                const int d = warp + 8 * k;
                float4 v = *reinterpret_cast<const float4*>(&St[(MAXD - d) * SP + iq]);
                v.x *= scale; v.y *= scale; v.z *= scale; v.w *= scale;
                *reinterpret_cast<float4*>(
                    out + (((size_t)b * MAXD + d) * HDIM + h) * WDIM + w0 + iq) = v;
            }
            // St WAR vs next scatter: 4 steps away, barriers in between.
        }
    }
}

extern "C" void kernel_launch(void* const* d_in, const int* in_sizes, int n_in,
                              void* d_out, int out_size) {
    const float* x = (const float*)d_in[0];
    const float* y = (const float*)d_in[1];
    float* out = (float*)d_out;

    cudaFuncSetAttribute(corr_mma,
                         cudaFuncAttributeMaxDynamicSharedMemorySize, SMEM_BYTES);

    dim3 grid(WDIM / MT, HDIM / HC, BDIM);   // (4, 32, 8) = 1024 blocks
    corr_mma<<<grid, NTHR, SMEM_BYTES>>>(x, y, out);
}

// round 14
// speedup vs baseline: 1.5432x; 1.0843x over previous
#include <cuda_runtime.h>
#include <cstdint>

// Correlation cost volume via banded fp16 mma.sync (m16n8k16, fp32 accum),
// software-pipelined over (h, k-chunk) with cp.async double-buffering;
// 3 blocks/SM. fp16 has the same 10-bit mantissa as tf32 -> same precision
// class (rel_err ~3e-4), but k16 halves MMA count and cvt count vs tf32 k8.
// out[b,d,h,w] = mean_c( x[b,c,h,w] * y[b,c,h,w-d] ), 0 where w<d (exact via
// zero-padded halo; cp.async zfill).
// Per (b,h,wtile=128): A[i,k]=x[k,w0+i] (128x32), B[s,k]=y[k,w0-48+s] (176x32),
// P = A.B^T banded; warp m computes rows [16m,16m+16) x cols [16m,16m+64).
// K streamed in 2 chunks of 16 channels (= one k16 MMA step each).
// d = 48-(s-i); epilogue stages to St[48-d][i] so per-d gather is a contig row.

#define BDIM 8
#define CDIM 32
#define HDIM 256
#define WDIM 512
#define MAXD 48

#define MT   128
#define NT   176
#define NTHR 256
#define HC   8                  // h rows per block
#define KC   16                 // channels per pipeline chunk = one k16 step
#define NSTEPS (HC * 2)

#define AP 132                  // A pitch (words): 2*AP%32==8 -> k-pair loads conflict-free
#define BP 180                  // B pitch (words): 2*BP%32==8 -> conflict-free
#define SP 136                  // stage pitch (words)
#define A_WORDS (KC * AP)       // 2112
#define B_WORDS (KC * BP)       // 2880
#define BUF_WORDS (A_WORDS + B_WORDS)       // 4992 (~19.5 KB)
#define ST_OFF  (2 * BUF_WORDS)             // 9984
#define ST_WORDS ((MAXD + 1) * SP)          // 6664
#define SMEM_BYTES ((ST_OFF + ST_WORDS) * 4)  // 66592 B -> 3 blocks/SM

#define A_CHUNKS (KC * (MT / 4))   // 512 16B chunks per step
#define B_CHUNKS (KC * (NT / 4))   // 704

// pack two fp32 -> f16x2 reg with lo = v0, hi = v1 (one instruction)
__device__ __forceinline__ uint32_t pack16(float v0, float v1) {
    uint32_t r;
    asm("cvt.rn.f16x2.f32 %0, %1, %2;" : "=r"(r) : "f"(v1), "f"(v0));
    return r;
}
__device__ __forceinline__ uint32_t smem_u32(const void* p) {
    uint32_t a;
    asm("{ .reg .u64 t; cvta.to.shared.u64 t, %1; cvt.u32.u64 %0, t; }" : "=r"(a) : "l"(p));
    return a;
}
__device__ __forceinline__ void cp16(uint32_t dst, const void* src, int src_sz) {
    asm volatile("cp.async.cg.shared.global [%0], [%1], 16, %2;"
                 :: "r"(dst), "l"(src), "r"(src_sz) : "memory");
}
__device__ __forceinline__ void mma_f16(float* c, const uint32_t* a,
                                        uint32_t b0, uint32_t b1) {
    asm volatile(
        "mma.sync.aligned.m16n8k16.row.col.f32.f16.f16.f32 "
        "{%0,%1,%2,%3}, {%4,%5,%6,%7}, {%8,%9}, {%0,%1,%2,%3};"
        : "+f"(c[0]), "+f"(c[1]), "+f"(c[2]), "+f"(c[3])
        : "r"(a[0]), "r"(a[1]), "r"(a[2]), "r"(a[3]), "r"(b0), "r"(b1));
}

__global__ __launch_bounds__(NTHR, 3)
void corr_mma(const float* __restrict__ x, const float* __restrict__ y,
              float* __restrict__ out) {
    extern __shared__ float smem[];
    const uint32_t sb = smem_u32(smem);

    const int tid  = threadIdx.x;
    const int warp = tid >> 5, lane = tid & 31;
    const int w0    = blockIdx.x * MT;
    const int hbase = blockIdx.y * HC;
    const int b     = blockIdx.z;

    const size_t plane = (size_t)HDIM * WDIM;
    const float* xb = x + (size_t)b * CDIM * plane;
    const float* yb = y + (size_t)b * CDIM * plane;

    // ---- cp.async staging of one 16-channel K-chunk of (A,B) for step s ----
    auto issue_stage = [&](int s) {
        const int hh = s >> 1, kc = s & 1, pb = s & 1;
        const float* xr = xb + (size_t)(hbase + hh) * WDIM + (size_t)(kc * KC) * plane;
        const float* yr = yb + (size_t)(hbase + hh) * WDIM + (size_t)(kc * KC) * plane;
        const uint32_t abase = sb + (pb * BUF_WORDS) * 4;
        const uint32_t bbase = abase + A_WORDS * 4;
        #pragma unroll 2
        for (int i = tid; i < A_CHUNKS + B_CHUNKS; i += NTHR) {
            if (i < A_CHUNKS) {
                const int k = i >> 5, v = (i & 31) << 2;
                cp16(abase + (k * AP + v) * 4, xr + k * plane + w0 + v, 16);
            } else {
                const int j = i - A_CHUNKS;
                const int k = j / (NT / 4), v = (j % (NT / 4)) << 2;
                const int gw = w0 - MAXD + v;
                cp16(bbase + (k * BP + v) * 4,
                     yr + k * plane + (gw >= 0 ? gw : 0), gw >= 0 ? 16 : 0);
            }
        }
    };

    issue_stage(0);
    asm volatile("cp.async.commit_group;" ::: "memory");

    const int i0 = 16 * warp;
    const int r  = lane >> 2;     // 0..7
    const int cq = lane & 3;      // 0..3
    float* St = smem + ST_OFF;

    float acc[8][4];

    for (int step = 0; step < NSTEPS; step++) {
        const int kc = step & 1;
        const int p  = step & 1;

        // depth-2: issue next step's copy first (hides behind this full step).
        // Safe: its target buffer's last readers (step-1 MMA) are behind the
        // end-of-step barrier every step executes.
        if (step + 1 < NSTEPS) {
            issue_stage(step + 1);
            asm volatile("cp.async.commit_group;" ::: "memory");
            asm volatile("cp.async.wait_group 1;" ::: "memory");
        } else {
            asm volatile("cp.async.wait_group 0;" ::: "memory");
        }
        __syncthreads();   // buffer p's data visible to all threads

        if (kc == 0) {
            #pragma unroll
            for (int t = 0; t < 8; t++)
                #pragma unroll
                for (int q = 0; q < 4; q++) acc[t][q] = 0.f;
        }

        // ---- banded MMA: one m16n8k16 step over this 16-channel chunk ----
        const float* As = smem + p * BUF_WORDS;   // [KC][AP] fp32
        const float* Bs = As + A_WORDS;           // [KC][BP] fp32

        // A fragment (16x16): reg pairs along k = (2cq, 2cq+1) and (+8)
        uint32_t a[4];
        a[0] = pack16(As[(2 * cq)     * AP + i0 + r],     As[(2 * cq + 1) * AP + i0 + r]);
        a[1] = pack16(As[(2 * cq)     * AP + i0 + r + 8], As[(2 * cq + 1) * AP + i0 + r + 8]);
        a[2] = pack16(As[(2 * cq + 8) * AP + i0 + r],     As[(2 * cq + 9) * AP + i0 + r]);
        a[3] = pack16(As[(2 * cq + 8) * AP + i0 + r + 8], As[(2 * cq + 9) * AP + i0 + r + 8]);

        #pragma unroll
        for (int t = 0; t < 8; t++) {
            const int s0 = i0 + 8 * t;
            uint32_t b0 = pack16(Bs[(2 * cq)     * BP + s0 + r], Bs[(2 * cq + 1) * BP + s0 + r]);
            uint32_t b1 = pack16(Bs[(2 * cq + 8) * BP + s0 + r], Bs[(2 * cq + 9) * BP + s0 + r]);
            mma_f16(acc[t], a, b0, b1);
        }

        if (kc == 0) {
            __syncthreads();   // end-of-step barrier (orders MMA reads before
                               // the refill of this buffer issued at step+2)
        } else {
            // ---- scatter into shift-normalized stage St[u = 48-d][i] ----
            #pragma unroll
            for (int t = 0; t < 8; t++) {
                #pragma unroll
                for (int q = 0; q < 4; q++) {
                    const int re = r + (q >= 2 ? 8 : 0);
                    const int sl = 8 * t + 2 * cq + (q & 1);
                    const int u  = sl - re;
                    if (u >= 1 && u <= MAXD)
                        St[u * SP + i0 + re] = acc[t][q];
                }
            }
            __syncthreads();   // doubles as end-of-step barrier

            // ---- gather row u = 48-d (contiguous) + coalesced STG.128 ----
            const int h = hbase + (step >> 1);
            const float scale = 1.0f / (float)CDIM;
            const int iq = 4 * lane;
            #pragma unroll
            for (int k = 0; k < 6; k++) {
                const int d = warp + 8 * k;
                float4 v = *reinterpret_cast<const float4*>(&St[(MAXD - d) * SP + iq]);
                v.x *= scale; v.y *= scale; v.z *= scale; v.w *= scale;
                *reinterpret_cast<float4*>(
                    out + (((size_t)b * MAXD + d) * HDIM + h) * WDIM + w0 + iq) = v;
            }
            // St WAR vs next scatter: 2 steps away, barriers in between.
        }
    }
}

extern "C" void kernel_launch(void* const* d_in, const int* in_sizes, int n_in,
                              void* d_out, int out_size) {
    const float* x = (const float*)d_in[0];
    const float* y = (const float*)d_in[1];
    float* out = (float*)d_out;

    cudaFuncSetAttribute(corr_mma,
                         cudaFuncAttributeMaxDynamicSharedMemorySize, SMEM_BYTES);

    dim3 grid(WDIM / MT, HDIM / HC, BDIM);   // (4, 32, 8) = 1024 blocks
    corr_mma<<<grid, NTHR, SMEM_BYTES>>>(x, y, out);
}

// round 15
// speedup vs baseline: 1.5733x; 1.0195x over previous
#include <cuda_runtime.h>
#include <cstdint>

// Correlation cost volume via banded fp16 mma.sync (m16n8k16, fp32 accum),
// PERSISTENT blocks (single wave, no wave-quantization tail), cp.async
// double-buffered pipeline continuous across tile boundaries; 3 blocks/SM.
// out[b,d,h,w] = mean_c( x[b,c,h,w] * y[b,c,h,w-d] ), 0 where w<d (exact via
// zero-padded halo; cp.async zfill).
// Tile = one (b, h, w-tile of 128): A[i,k]=x[k,w0+i] (128x32),
// B[s,k]=y[k,w0-48+s] (176x32), P = A.B^T banded; warp m computes rows
// [16m,16m+16) x cols [16m,16m+64). K streamed in 2 chunks of 16 channels
// (one m16n8k16 step each); accumulators persist across the 2 chunks.
// d = 48-(s-i); epilogue stages to St[48-d][i] so per-d gather is contiguous.
//
// R15 vs R14: grid 1024 -> 444 persistent blocks, each looping over tiles
// bid, bid+444, ... The depth-2 pipeline streams across tiles, so the chip
// runs ONE full wave (previously 2.31 waves -> 31%-full tail wasted ~20%).

#define BDIM 8
#define CDIM 32
#define HDIM 256
#define WDIM 512
#define MAXD 48

#define MT   128
#define NT   176
#define NTHR 256
#define GRID 444                  // 148 SMs x 3 blocks: one wave (<= 152x3 too)
#define NTILES (BDIM * HDIM * (WDIM / MT))   // 8192
#define KC   16                   // channels per pipeline step (one k16 MMA)

#define AP 132                    // A pitch (words): k-pair frag loads conflict-free
#define BP 180                    // B pitch (words): conflict-free
#define SP 136                    // stage pitch (words)
#define A_WORDS (KC * AP)         // 2112
#define B_WORDS (KC * BP)         // 2880
#define BUF_WORDS (A_WORDS + B_WORDS)       // 4992 (~19.5 KB)
#define ST_OFF  (2 * BUF_WORDS)             // 9984
#define ST_WORDS ((MAXD + 1) * SP)          // 6664
#define SMEM_BYTES ((ST_OFF + ST_WORDS) * 4)  // 66592 B -> 3 blocks/SM

#define A_CHUNKS (KC * (MT / 4))  // 512 16B chunks per step
#define B_CHUNKS (KC * (NT / 4))  // 704

__device__ __forceinline__ uint32_t pack16(float v0, float v1) {
    uint32_t r;   // f16x2 with lo = v0, hi = v1
    asm("cvt.rn.f16x2.f32 %0, %1, %2;" : "=r"(r) : "f"(v1), "f"(v0));
    return r;
}
__device__ __forceinline__ uint32_t smem_u32(const void* p) {
    uint32_t a;
    asm("{ .reg .u64 t; cvta.to.shared.u64 t, %1; cvt.u32.u64 %0, t; }" : "=r"(a) : "l"(p));
    return a;
}
__device__ __forceinline__ void cp16(uint32_t dst, const void* src, int src_sz) {
    asm volatile("cp.async.cg.shared.global [%0], [%1], 16, %2;"
                 :: "r"(dst), "l"(src), "r"(src_sz) : "memory");
}
__device__ __forceinline__ void mma_f16(float* c, const uint32_t* a,
                                        uint32_t b0, uint32_t b1) {
    asm volatile(
        "mma.sync.aligned.m16n8k16.row.col.f32.f16.f16.f32 "
        "{%0,%1,%2,%3}, {%4,%5,%6,%7}, {%8,%9}, {%0,%1,%2,%3};"
        : "+f"(c[0]), "+f"(c[1]), "+f"(c[2]), "+f"(c[3])
        : "r"(a[0]), "r"(a[1]), "r"(a[2]), "r"(a[3]), "r"(b0), "r"(b1));
}

__global__ __launch_bounds__(NTHR, 3)
void corr_mma(const float* __restrict__ x, const float* __restrict__ y,
              float* __restrict__ out) {
    extern __shared__ float smem[];
    const uint32_t sb = smem_u32(smem);

    const int tid  = threadIdx.x;
    const int warp = tid >> 5, lane = tid & 31;
    const int bid  = blockIdx.x;

    const size_t plane = (size_t)HDIM * WDIM;

    // tiles bid, bid+GRID, ... < NTILES; 2 pipeline steps per tile
    const int ntiles = (NTILES - bid + GRID - 1) / GRID;
    const int nsteps = 2 * ntiles;

    // ---- stage one 16-channel K-chunk of (A,B) for local step ls ----
    auto issue_stage = [&](int ls) {
        const int ti = bid + GRID * (ls >> 1);      // tile id
        const int kc = ls & 1, pb = ls & 1;
        const int w0 = (ti & 3) * MT;
        const int h  = (ti >> 2) & (HDIM - 1);
        const int b  = ti >> 10;
        const float* xr = x + ((size_t)b * CDIM + kc * KC) * plane + (size_t)h * WDIM;
        const float* yr = y + ((size_t)b * CDIM + kc * KC) * plane + (size_t)h * WDIM;
        const uint32_t abase = sb + (pb * BUF_WORDS) * 4;
        const uint32_t bbase = abase + A_WORDS * 4;
        #pragma unroll 2
        for (int i = tid; i < A_CHUNKS + B_CHUNKS; i += NTHR) {
            if (i < A_CHUNKS) {
                const int k = i >> 5, v = (i & 31) << 2;
                cp16(abase + (k * AP + v) * 4, xr + k * plane + w0 + v, 16);
            } else {
                const int j = i - A_CHUNKS;
                const int k = j / (NT / 4), v = (j % (NT / 4)) << 2;
                const int gw = w0 - MAXD + v;
                cp16(bbase + (k * BP + v) * 4,
                     yr + k * plane + (gw >= 0 ? gw : 0), gw >= 0 ? 16 : 0);
            }
        }
    };

    issue_stage(0);
    asm volatile("cp.async.commit_group;" ::: "memory");

    const int i0 = 16 * warp;
    const int r  = lane >> 2;     // 0..7
    const int cq = lane & 3;      // 0..3
    float* St = smem + ST_OFF;

    float acc[8][4];

    for (int ls = 0; ls < nsteps; ls++) {
        const int kc = ls & 1;
        const int p  = ls & 1;

        // depth-2: issue next step's copy first (hides behind this full step).
        // Safe: its buffer's last readers (step ls-1 MMA) are behind the
        // end-of-step barrier every step executes.
        if (ls + 1 < nsteps) {
            issue_stage(ls + 1);
            asm volatile("cp.async.commit_group;" ::: "memory");
            asm volatile("cp.async.wait_group 1;" ::: "memory");
        } else {
            asm volatile("cp.async.wait_group 0;" ::: "memory");
        }
        __syncthreads();   // buffer p's data visible to all threads

        if (kc == 0) {
            #pragma unroll
            for (int t = 0; t < 8; t++)
                #pragma unroll
                for (int q = 0; q < 4; q++) acc[t][q] = 0.f;
        }

        // ---- banded MMA: one m16n8k16 step over this 16-channel chunk ----
        const float* As = smem + p * BUF_WORDS;   // [KC][AP] fp32
        const float* Bs = As + A_WORDS;           // [KC][BP] fp32

        uint32_t a[4];
        a[0] = pack16(As[(2 * cq)     * AP + i0 + r],     As[(2 * cq + 1) * AP + i0 + r]);
        a[1] = pack16(As[(2 * cq)     * AP + i0 + r + 8], As[(2 * cq + 1) * AP + i0 + r + 8]);
        a[2] = pack16(As[(2 * cq + 8) * AP + i0 + r],     As[(2 * cq + 9) * AP + i0 + r]);
        a[3] = pack16(As[(2 * cq + 8) * AP + i0 + r + 8], As[(2 * cq + 9) * AP + i0 + r + 8]);

        #pragma unroll
        for (int t = 0; t < 8; t++) {
            const int s0 = i0 + 8 * t;
            uint32_t b0 = pack16(Bs[(2 * cq)     * BP + s0 + r], Bs[(2 * cq + 1) * BP + s0 + r]);
            uint32_t b1 = pack16(Bs[(2 * cq + 8) * BP + s0 + r], Bs[(2 * cq + 9) * BP + s0 + r]);
            mma_f16(acc[t], a, b0, b1);
        }

        if (kc == 0) {
            __syncthreads();   // end-of-step barrier (orders MMA reads before
                               // this buffer's refill issued at step ls+2)
        } else {
            // ---- scatter into shift-normalized stage St[u = 48-d][i] ----
            #pragma unroll
            for (int t = 0; t < 8; t++) {
                #pragma unroll
                for (int q = 0; q < 4; q++) {
                    const int re = r + (q >= 2 ? 8 : 0);
                    const int sl = 8 * t + 2 * cq + (q & 1);
                    const int u  = sl - re;
                    if (u >= 1 && u <= MAXD)
                        St[u * SP + i0 + re] = acc[t][q];
                }
            }
            __syncthreads();   // doubles as end-of-step barrier

            // ---- gather row u = 48-d (contiguous) + coalesced STG.128 ----
            const int ti = bid + GRID * (ls >> 1);
            const int w0 = (ti & 3) * MT;
            const int h  = (ti >> 2) & (HDIM - 1);
            const int b  = ti >> 10;
            const float scale = 1.0f / (float)CDIM;
            const int iq = 4 * lane;
            #pragma unroll
            for (int k = 0; k < 6; k++) {
                const int d = warp + 8 * k;
                float4 v = *reinterpret_cast<const float4*>(&St[(MAXD - d) * SP + iq]);
                v.x *= scale; v.y *= scale; v.z *= scale; v.w *= scale;
                *reinterpret_cast<float4*>(
                    out + (((size_t)b * MAXD + d) * HDIM + h) * WDIM + w0 + iq) = v;
            }
            // St WAR vs next scatter: 2 steps away, barriers in between.
        }
    }
}

extern "C" void kernel_launch(void* const* d_in, const int* in_sizes, int n_in,
                              void* d_out, int out_size) {
    const float* x = (const float*)d_in[0];
    const float* y = (const float*)d_in[1];
    float* out = (float*)d_out;

    cudaFuncSetAttribute(corr_mma,
                         cudaFuncAttributeMaxDynamicSharedMemorySize, SMEM_BYTES);

    corr_mma<<<GRID, NTHR, SMEM_BYTES>>>(x, y, out);
}